// round 6
// baseline (speedup 1.0000x reference)
#include <cuda_runtime.h>
#include <cstdint>

#define DISP 49
#define GROUP 8
#define CPG 8
#define HH 96
#define WW 320
#define BB 2
#define EPSN 1e-5f
#define CHW (HH*WW)
#define PADE 49              // zero entries for the left pad
#define NE (PADE + WW)       // 369 entries * 32 B per row = 11808 B
#define ROWB 12288           // row stride padded to 1 KB multiple: swizzle-closed

typedef unsigned long long u64;

__device__ __forceinline__ uint32_t swz(uint32_t o) {
    // XOR bits[6:4] with bits[9:7]: bijective within each full 1 KB block,
    // keeps 16B alignment. Row regions are 1KB-aligned and 1KB-multiple sized.
    return o ^ ((o >> 3) & 0x70);
}
__device__ __forceinline__ u64 add2(u64 a, u64 b) {
    u64 r; asm("add.rn.f32x2 %0, %1, %2;" : "=l"(r) : "l"(a), "l"(b)); return r;
}
__device__ __forceinline__ u64 pack2(float lo, float hi) {
    u64 r; asm("mov.b64 %0, {%1, %2};" : "=l"(r) : "f"(lo), "f"(hi)); return r;
}
__device__ __forceinline__ void unpack2(u64 a, float& lo, float& hi) {
    asm("mov.b64 {%0, %1}, %2;" : "=f"(lo), "=f"(hi) : "l"(a));
}

// L1 cost over 8 channels (4 packed pairs). Pairs 0-2: abs via LOP3 mask,
// summed packed on the fma pipe; pair 3: abs free via FADD operand modifiers.
__device__ __forceinline__ float cost8(const u64 (&xp)[4], const u64 (&wp)[4]) {
    const u64 M = 0x7fffffff7fffffffULL;
    u64 d0 = add2(xp[0], wp[0]) & M;
    u64 d1 = add2(xp[1], wp[1]) & M;
    u64 d2 = add2(xp[2], wp[2]) & M;
    u64 d3 = add2(xp[3], wp[3]);
    u64 t  = add2(add2(d0, d1), d2);
    float tl, th, dl, dh;
    unpack2(t, tl, th);
    unpack2(d3, dl, dh);
    return (tl + th) + (fabsf(dl) + fabsf(dh));
}

// One disparity step: 4 outputs/thread, 4-slot sliding register window of
// NEGATED yn entries (entry e lives in slot e&3). DM = d & 3 compile-time.
// Compute p3 first (frees slot (3-DM)&3), refill it from smem (first consumed
// by NEXT step's p0 -> LDS latency covered), then p2..p0, one STG.128.
template<int DM>
__device__ __forceinline__ void step(const u64 (&xn)[4][4], u64 (&Wn)[4][4],
                                     const char* yns, int& bo, float4*& op) {
    const int sf = (3 - DM) & 3;
    float r3 = cost8(xn[3], Wn[sf]);
    {
        const ulonglong2 lo = *(const ulonglong2*)(yns + swz((uint32_t)bo));
        const ulonglong2 hi = *(const ulonglong2*)(yns + swz((uint32_t)bo + 16u));
        Wn[sf][0] = lo.x; Wn[sf][1] = lo.y;
        Wn[sf][2] = hi.x; Wn[sf][3] = hi.y;
    }
    float r2 = cost8(xn[2], Wn[(2 - DM) & 3]);
    float r1 = cost8(xn[1], Wn[(1 - DM) & 3]);
    float r0 = cost8(xn[0], Wn[(0 - DM) & 3]);
    *op = make_float4(r0, r1, r2, r3);
    op += CHW / 4;
    bo -= 32;
}

__global__ __launch_bounds__(160, 3)
void cost_volume_kernel(const float* __restrict__ x,
                        const float* __restrict__ y,
                        float* __restrict__ out) {
    __shared__ __align__(1024) char yns_all[2][ROWB];

    const int lx = threadIdx.x;          // 0..79, owns w = 4lx .. 4lx+3
    const int r  = threadIdx.y;          // 0..1
    const int h  = blockIdx.x * 2 + r;
    const int g  = blockIdx.y;
    const int b  = blockIdx.z;
    const int w0 = lx * 4;
    char* yns = yns_all[r];

    // zero-fill pad entries (-49..-1): pad cost Σ|xn-0| emerges naturally
    if (lx < PADE) {
        const uint32_t bz = (uint32_t)lx * 32u;
        *(ulonglong2*)(yns + swz(bz))       = make_ulonglong2(0ULL, 0ULL);
        *(ulonglong2*)(yns + swz(bz + 16u)) = make_ulonglong2(0ULL, 0ULL);
    }

    const float4* xp = (const float4*)(x + ((b * 64 + g * CPG) * HH + h) * WW) + lx;
    const float4* yp = (const float4*)(y + ((b * 64 + g * CPG) * HH + h) * WW) + lx;

    float xv[4][CPG], yv[4][CPG];
    float sx[4] = {0, 0, 0, 0}, sy[4] = {0, 0, 0, 0};
#pragma unroll
    for (int c = 0; c < CPG; c++) {
        const float4 tx = xp[c * (CHW / 4)];
        const float4 ty = yp[c * (CHW / 4)];
        xv[0][c] = tx.x; xv[1][c] = tx.y; xv[2][c] = tx.z; xv[3][c] = tx.w;
        yv[0][c] = ty.x; yv[1][c] = ty.y; yv[2][c] = ty.z; yv[3][c] = ty.w;
#pragma unroll
        for (int p = 0; p < 4; p++) {
            sx[p] += xv[p][c] * xv[p][c];
            sy[p] += yv[p][c] * yv[p][c];
        }
    }

    u64 xn[4][4];
    u64 Wn[4][4];
#pragma unroll
    for (int p = 0; p < 4; p++) {
        const float ix =  1.f / (sqrtf(sx[p]) + EPSN);
        const float iy = -1.f / (sqrtf(sy[p]) + EPSN);   // negated: diff = add2
#pragma unroll
        for (int q = 0; q < 4; q++) {
            xn[p][q] = pack2(xv[p][2 * q] * ix, xv[p][2 * q + 1] * ix);
            Wn[p][q] = pack2(yv[p][2 * q] * iy, yv[p][2 * q + 1] * iy);
        }
    }

    // publish -yn (entry w0+p -> slot p = (w0+p)&3, matching window init)
#pragma unroll
    for (int p = 0; p < 4; p++) {
        const uint32_t bz = (uint32_t)(w0 + p + PADE) * 32u;
        *(ulonglong2*)(yns + swz(bz))       = make_ulonglong2(Wn[p][0], Wn[p][1]);
        *(ulonglong2*)(yns + swz(bz + 16u)) = make_ulonglong2(Wn[p][2], Wn[p][3]);
    }
    __syncthreads();

    float4* op = (float4*)(out + ((b * GROUP + g) * DISP * HH + h) * WW) + lx;
    int bo = (w0 - 1 + PADE) * 32;       // first refill: entry w0 - 1

    step<0>(xn, Wn, yns, bo, op);
#pragma unroll
    for (int i = 0; i < 12; i++) {
        step<1>(xn, Wn, yns, bo, op);
        step<2>(xn, Wn, yns, bo, op);
        step<3>(xn, Wn, yns, bo, op);
        step<0>(xn, Wn, yns, bo, op);
    }
}

extern "C" void kernel_launch(void* const* d_in, const int* in_sizes, int n_in,
                              void* d_out, int out_size) {
    const float* x = (const float*)d_in[0];
    const float* y = (const float*)d_in[1];
    float* out = (float*)d_out;

    dim3 grid(HH / 2, GROUP, BB);   // 48 x 8 x 2 = 768 CTAs
    dim3 block(80, 2);              // 160 threads: 2 rows x 80 (4 w each)
    cost_volume_kernel<<<grid, block>>>(x, y, out);
}

// round 8
// speedup vs baseline: 1.0718x; 1.0718x over previous
#include <cuda_runtime.h>
#include <cstdint>

#define DISP 49
#define GROUP 8
#define CPG 8
#define HH 96
#define WW 320
#define BB 2
#define EPSN 1e-5f
#define CHW (HH*WW)
#define PADE 49              // zero entries for the left pad
#define ROWB 12288           // per-row smem stride: 1 KB multiple (swizzle-closed)

typedef unsigned long long u64;

__device__ __forceinline__ uint32_t swz(uint32_t o) {
    // XOR bits[6:4] with bits[9:7]: bijective within each full 1 KB block
    return o ^ ((o >> 3) & 0x70);
}
// For 32-aligned o: swz(o+16) = swz(o) ^ 16  (XOR, NOT add — the mask may
// itself carry bit 4). Row bases are 1024-aligned so XOR on the generic
// pointer's low bits is exact.
__device__ __forceinline__ const char* x16(const char* p) {
    return (const char*)((uintptr_t)p ^ 16u);
}
__device__ __forceinline__ char* x16(char* p) {
    return (char*)((uintptr_t)p ^ 16u);
}
__device__ __forceinline__ u64 add2(u64 a, u64 b) {
    u64 r; asm("add.rn.f32x2 %0, %1, %2;" : "=l"(r) : "l"(a), "l"(b)); return r;
}
__device__ __forceinline__ u64 pack2(float lo, float hi) {
    u64 r; asm("mov.b64 %0, {%1, %2};" : "=l"(r) : "f"(lo), "f"(hi)); return r;
}
__device__ __forceinline__ void unpack2(u64 a, float& lo, float& hi) {
    asm("mov.b64 {%0, %1}, %2;" : "=f"(lo), "=f"(hi) : "l"(a));
}

// L1 cost over 8 channels (4 packed pairs). Pairs 0-2: abs via LOP3 mask,
// summed packed (fma pipe); pair 3: abs free via FADD operand modifiers.
__device__ __forceinline__ float cost8(const u64 (&xp)[4], const u64 (&wp)[4]) {
    const u64 M = 0x7fffffff7fffffffULL;
    u64 d0 = add2(xp[0], wp[0]) & M;
    u64 d1 = add2(xp[1], wp[1]) & M;
    u64 d2 = add2(xp[2], wp[2]) & M;
    u64 d3 = add2(xp[3], wp[3]);
    u64 t  = add2(add2(d0, d1), d2);
    float tl, th, dl, dh;
    unpack2(t, tl, th);
    unpack2(d3, dl, dh);
    return (tl + th) + (fabsf(dl) + fabsf(dh));
}

// One disparity step: 4 outputs/thread, 4-slot sliding register window of
// NEGATED yn entries (entry e -> slot e&3). DM = d & 3 compile-time.
// p3 first (frees slot (3-DM)&3), refill it (consumed only by NEXT step's
// p0 -> LDS latency covered), then p2..p0, one STG.128.
template<int DM>
__device__ __forceinline__ void step(const u64 (&xn)[4][4], u64 (&Wn)[4][4],
                                     const char* yns, int& bo, float4*& op) {
    const int sf = (3 - DM) & 3;
    float r3 = cost8(xn[3], Wn[sf]);
    {
        const char* a = yns + swz((uint32_t)bo);
        const ulonglong2 lo = *(const ulonglong2*)(a);
        const ulonglong2 hi = *(const ulonglong2*)(x16(a));  // swz(bo)^16
        Wn[sf][0] = lo.x; Wn[sf][1] = lo.y;
        Wn[sf][2] = hi.x; Wn[sf][3] = hi.y;
    }
    float r2 = cost8(xn[2], Wn[(2 - DM) & 3]);
    float r1 = cost8(xn[1], Wn[(1 - DM) & 3]);
    float r0 = cost8(xn[0], Wn[(0 - DM) & 3]);
    *op = make_float4(r0, r1, r2, r3);
    op += CHW / 4;
    bo -= 32;
}

__global__ __launch_bounds__(160, 4)
void cost_volume_kernel(const float* __restrict__ x,
                        const float* __restrict__ y,
                        float* __restrict__ out) {
    __shared__ __align__(1024) char yns_all[2][ROWB];

    const int lx = threadIdx.x;          // 0..79, owns w = 4lx .. 4lx+3
    const int r  = threadIdx.y;          // 0..1
    const int h  = blockIdx.x * 2 + r;
    const int g  = blockIdx.y;
    const int b  = blockIdx.z;
    const int w0 = lx * 4;
    char* yns = yns_all[r];

    // zero-fill pad entries (-49..-1): pad cost Σ|xn-0| emerges naturally
    if (lx < PADE) {
        char* a = yns + swz((uint32_t)lx * 32u);
        *(ulonglong2*)(a)      = make_ulonglong2(0ULL, 0ULL);
        *(ulonglong2*)(x16(a)) = make_ulonglong2(0ULL, 0ULL);
    }

    const float4* xp = (const float4*)(x + ((b * 64 + g * CPG) * HH + h) * WW) + lx;
    const float4* yp = (const float4*)(y + ((b * 64 + g * CPG) * HH + h) * WW) + lx;

    float xv[4][CPG], yv[4][CPG];
    float sx[4] = {0, 0, 0, 0}, sy[4] = {0, 0, 0, 0};
#pragma unroll
    for (int c = 0; c < CPG; c++) {
        const float4 tx = xp[c * (CHW / 4)];
        const float4 ty = yp[c * (CHW / 4)];
        xv[0][c] = tx.x; xv[1][c] = tx.y; xv[2][c] = tx.z; xv[3][c] = tx.w;
        yv[0][c] = ty.x; yv[1][c] = ty.y; yv[2][c] = ty.z; yv[3][c] = ty.w;
#pragma unroll
        for (int p = 0; p < 4; p++) {
            sx[p] += xv[p][c] * xv[p][c];
            sy[p] += yv[p][c] * yv[p][c];
        }
    }

    u64 xn[4][4];
    u64 Wn[4][4];
#pragma unroll
    for (int p = 0; p < 4; p++) {
        const float ix =  1.f / (sqrtf(sx[p]) + EPSN);
        const float iy = -1.f / (sqrtf(sy[p]) + EPSN);   // negated: diff = add2
#pragma unroll
        for (int q = 0; q < 4; q++) {
            xn[p][q] = pack2(xv[p][2 * q] * ix, xv[p][2 * q + 1] * ix);
            Wn[p][q] = pack2(yv[p][2 * q] * iy, yv[p][2 * q + 1] * iy);
        }
    }

    // publish -yn (entry w0+p -> slot p = (w0+p)&3, matching window init)
#pragma unroll
    for (int p = 0; p < 4; p++) {
        char* a = yns + swz((uint32_t)(w0 + p + PADE) * 32u);
        *(ulonglong2*)(a)      = make_ulonglong2(Wn[p][0], Wn[p][1]);
        *(ulonglong2*)(x16(a)) = make_ulonglong2(Wn[p][2], Wn[p][3]);
    }
    __syncthreads();

    float4* op = (float4*)(out + ((b * GROUP + g) * DISP * HH + h) * WW) + lx;
    int bo = (w0 - 1 + PADE) * 32;       // first refill: entry w0 - 1

    step<0>(xn, Wn, yns, bo, op);
#pragma unroll
    for (int i = 0; i < 12; i++) {
        step<1>(xn, Wn, yns, bo, op);
        step<2>(xn, Wn, yns, bo, op);
        step<3>(xn, Wn, yns, bo, op);
        step<0>(xn, Wn, yns, bo, op);
    }
}

extern "C" void kernel_launch(void* const* d_in, const int* in_sizes, int n_in,
                              void* d_out, int out_size) {
    const float* x = (const float*)d_in[0];
    const float* y = (const float*)d_in[1];
    float* out = (float*)d_out;

    dim3 grid(HH / 2, GROUP, BB);   // 768 CTAs
    dim3 block(80, 2);              // 160 threads: 2 rows x 80 (4 w each)
    cost_volume_kernel<<<grid, block>>>(x, y, out);
}

// round 9
// speedup vs baseline: 1.2119x; 1.1306x over previous
#include <cuda_runtime.h>
#include <cstdint>

#define DISP 49
#define GROUP 8
#define CPG 8
#define HH 96
#define WW 320
#define BB 2
#define EPSN 1e-5f
#define CHW (HH*WW)
#define PADE 49              // zero entries for the left pad
#define ROWB 12288           // smem row size: 1 KB multiple (swizzle-closed)

typedef unsigned long long u64;

__device__ __forceinline__ uint32_t swz(uint32_t o) {
    // XOR bits[6:4] with bits[9:7]: bijective within each full 1 KB block
    return o ^ ((o >> 3) & 0x70);
}
// For 32-aligned o: swz(o+16) = swz(o) ^ 16 (bit 4 of o is 0; mask unaffected
// by +16). Row base is 1024-aligned so XOR on the pointer low bits is exact.
__device__ __forceinline__ const char* x16(const char* p) {
    return (const char*)((uintptr_t)p ^ 16u);
}
__device__ __forceinline__ char* x16(char* p) {
    return (char*)((uintptr_t)p ^ 16u);
}
__device__ __forceinline__ u64 add2(u64 a, u64 b) {
    u64 r; asm("add.rn.f32x2 %0, %1, %2;" : "=l"(r) : "l"(a), "l"(b)); return r;
}
__device__ __forceinline__ u64 pack2(float lo, float hi) {
    u64 r; asm("mov.b64 %0, {%1, %2};" : "=l"(r) : "f"(lo), "f"(hi)); return r;
}
__device__ __forceinline__ void unpack2(u64 a, float& lo, float& hi) {
    asm("mov.b64 {%0, %1}, %2;" : "=f"(lo), "=f"(hi) : "l"(a));
}

struct C2 { u64 t6; u64 d3; };   // packed 6-channel |diff| sums + raw pair-3 diff

// Pairs 0-2 abs'd via LOP3 mask and summed packed; pair 3 returned raw
// (abs folded later into scalar FADD operand modifiers -> free on fma pipe).
__device__ __forceinline__ C2 cost(const u64 (&xp)[4], const u64 (&wp)[4]) {
    const u64 M = 0x7fffffff7fffffffULL;
    u64 d0 = add2(xp[0], wp[0]) & M;
    u64 d1 = add2(xp[1], wp[1]) & M;
    u64 d2 = add2(xp[2], wp[2]) & M;
    u64 d3 = add2(xp[3], wp[3]);
    C2 c; c.t6 = add2(add2(d0, d1), d2); c.d3 = d3; return c;
}

// One disparity step: 2 outputs/thread. 3-slot sliding window of NEGATED yn
// entries; slot(offset o = entry - w0) = o mod 3, DM = d mod 3 compile-time.
// Refill (entry w0-d-1, consumed next step) is ISSUED FIRST -> ~1.5 steps of
// LDS-latency cover. Tail combines both outputs packed; single STG.64.
template<int DM>
__device__ __forceinline__ void step(const u64 (&xn)[2][4], u64 (&Wn)[3][4],
                                     const char* yns, int& bo, char*& op) {
    constexpr int S1 = ((1 - DM) % 3 + 3) % 3;   // slot of entry w0+1-d
    constexpr int S0 = ((0 - DM) % 3 + 3) % 3;   // slot of entry w0-d
    constexpr int SR = ((-1 - DM) % 3 + 3) % 3;  // refill slot (entry w0-d-1)

    const char* a = yns + swz((uint32_t)bo);
    const ulonglong2 lo = *(const ulonglong2*)(a);
    const ulonglong2 hi = *(const ulonglong2*)(x16(a));
    Wn[SR][0] = lo.x; Wn[SR][1] = lo.y;
    Wn[SR][2] = hi.x; Wn[SR][3] = hi.y;

    C2 c1 = cost(xn[1], Wn[S1]);
    C2 c0 = cost(xn[0], Wn[S0]);

    float a0, b0, a1, b1, t0l, t0h, t1l, t1h;
    unpack2(c0.d3, a0, b0);
    unpack2(c1.d3, a1, b1);
    unpack2(c0.t6, t0l, t0h);
    unpack2(c1.t6, t1l, t1h);
    const float s0 = fabsf(a0) + fabsf(b0);      // abs via FADD modifiers
    const float s1 = fabsf(a1) + fabsf(b1);
    const u64 res = add2(add2(pack2(t0l, t1l), pack2(t0h, t1h)), pack2(s0, s1));
    *(u64*)op = res;                              // STG.64: (r0, r1)
    op += (CHW / 2) * 8;
    bo -= 32;
}

__global__ __launch_bounds__(160, 6)
void cost_volume_kernel(const float* __restrict__ x,
                        const float* __restrict__ y,
                        float* __restrict__ out) {
    __shared__ __align__(1024) char yns[ROWB];

    const int lx = threadIdx.x;          // owns w = 2lx, 2lx+1
    const int h = blockIdx.x;
    const int g = blockIdx.y;
    const int b = blockIdx.z;
    const int w0 = lx * 2;

    // zero-fill pad entries (-49..-1): pad cost Σ|xn-0| emerges naturally
    if (lx < PADE) {
        char* a = yns + swz((uint32_t)lx * 32u);
        *(ulonglong2*)(a)      = make_ulonglong2(0ULL, 0ULL);
        *(ulonglong2*)(x16(a)) = make_ulonglong2(0ULL, 0ULL);
    }

    const float2* xp = (const float2*)(x + ((b * 64 + g * CPG) * HH + h) * WW) + lx;
    const float2* yp = (const float2*)(y + ((b * 64 + g * CPG) * HH + h) * WW) + lx;

    float xv[2][CPG], yv[2][CPG];
    float sx[2] = {0.f, 0.f}, sy[2] = {0.f, 0.f};
#pragma unroll
    for (int c = 0; c < CPG; c++) {
        const float2 tx = xp[c * (CHW / 2)];
        const float2 ty = yp[c * (CHW / 2)];
        xv[0][c] = tx.x; xv[1][c] = tx.y;
        yv[0][c] = ty.x; yv[1][c] = ty.y;
        sx[0] += tx.x * tx.x; sx[1] += tx.y * tx.y;
        sy[0] += ty.x * ty.x; sy[1] += ty.y * ty.y;
    }

    u64 xn[2][4];
    u64 Wn[3][4];
#pragma unroll
    for (int p = 0; p < 2; p++) {
        const float ix =  1.f / (sqrtf(sx[p]) + EPSN);
        const float iy = -1.f / (sqrtf(sy[p]) + EPSN);   // negated: diff = add2
#pragma unroll
        for (int q = 0; q < 4; q++) {
            xn[p][q] = pack2(xv[p][2 * q] * ix, xv[p][2 * q + 1] * ix);
            Wn[p][q] = pack2(yv[p][2 * q] * iy, yv[p][2 * q + 1] * iy);
        }
    }

    // publish -yn (entry w0+p -> offset p -> slot p, matching window init)
#pragma unroll
    for (int p = 0; p < 2; p++) {
        char* a = yns + swz((uint32_t)(w0 + p + PADE) * 32u);
        *(ulonglong2*)(a)      = make_ulonglong2(Wn[p][0], Wn[p][1]);
        *(ulonglong2*)(x16(a)) = make_ulonglong2(Wn[p][2], Wn[p][3]);
    }
    __syncthreads();

    char* op = (char*)((float2*)(out + ((b * GROUP + g) * DISP * HH + h) * WW) + lx);
    int bo = (w0 - 1 + PADE) * 32;       // step 0 refills entry w0 - 1

    // 49 steps = 1 + 16*3, phase DM = d mod 3
    step<0>(xn, Wn, yns, bo, op);
#pragma unroll 2
    for (int i = 0; i < 16; i++) {
        step<1>(xn, Wn, yns, bo, op);
        step<2>(xn, Wn, yns, bo, op);
        step<0>(xn, Wn, yns, bo, op);
    }
}

extern "C" void kernel_launch(void* const* d_in, const int* in_sizes, int n_in,
                              void* d_out, int out_size) {
    const float* x = (const float*)d_in[0];
    const float* y = (const float*)d_in[1];
    float* out = (float*)d_out;

    dim3 grid(HH, GROUP, BB);   // 1536 CTAs (one per b,g,h row)
    dim3 block(160);            // 5 warps, 2 w per thread
    cost_volume_kernel<<<grid, block>>>(x, y, out);
}